// round 1
// baseline (speedup 1.0000x reference)
#include <cuda_runtime.h>
#include <math_constants.h>
#include <cstdint>

// Problem constants
#define Bb   8
#define Ss   384
#define INd  512
#define Ee   512
#define Hh   8
#define Dd   64
#define Rr   767          // distinct rel values actually used (rows 128..894 of rel_table)
#define RP   768          // padded row stride for Ck/Cq
#define BHn  64           // B*H
#define MSn  3072         // B*S
#define SCALE_F 0.07216878364870322f   // 1/sqrt(64*3)

// ---------------- scratch (static device globals; no allocations) ----------------
static __device__ float g_Q  [MSn * Ee];
static __device__ float g_Km [MSn * Ee];
static __device__ float g_V  [MSn * Ee];
static __device__ float g_ctx[MSn * Ee];
static __device__ float g_Pk [Rr * Ee];
static __device__ float g_Pq [Rr * Ee];
static __device__ float g_Ck [(size_t)BHn * Ss * RP];   // [bh, i, r']  c2p gather source
static __device__ float g_Cq [(size_t)BHn * Ss * RP];   // [bh, j, r']  p2c gather source

// =====================================================================
// Generic SGEMM:  C[M,N] = A[M,K] @ W[N,K]^T + bias[N]
// 128x128 tile, BK=16, 256 threads, 8x8 per thread.
// =====================================================================
__global__ __launch_bounds__(256) void sgemm_bias(
    const float* __restrict__ A, const float* __restrict__ W,
    const float* __restrict__ bias, float* __restrict__ C,
    int M, int N, int K)
{
    __shared__ float As[16][128];
    __shared__ float Bs[16][128];

    const int tid = threadIdx.x;
    const int tm  = tid >> 4;          // 0..15
    const int tn  = tid & 15;          // 0..15
    const int m0  = blockIdx.y * 128;
    const int n0  = blockIdx.x * 128;

    const int lr = tid >> 2;           // 0..63
    const int lc = (tid & 3) << 2;     // 0,4,8,12  (float index of float4)

    float acc[8][8];
#pragma unroll
    for (int i = 0; i < 8; i++)
#pragma unroll
        for (int j = 0; j < 8; j++) acc[i][j] = 0.f;

    for (int k0 = 0; k0 < K; k0 += 16) {
#pragma unroll
        for (int it = 0; it < 2; it++) {
            int r  = lr + it * 64;
            int gm = m0 + r;
            float4 va = make_float4(0.f, 0.f, 0.f, 0.f);
            if (gm < M) va = *(const float4*)(A + (size_t)gm * K + k0 + lc);
            As[lc + 0][r] = va.x; As[lc + 1][r] = va.y;
            As[lc + 2][r] = va.z; As[lc + 3][r] = va.w;

            int gn = n0 + r;
            float4 vb = make_float4(0.f, 0.f, 0.f, 0.f);
            if (gn < N) vb = *(const float4*)(W + (size_t)gn * K + k0 + lc);
            Bs[lc + 0][r] = vb.x; Bs[lc + 1][r] = vb.y;
            Bs[lc + 2][r] = vb.z; Bs[lc + 3][r] = vb.w;
        }
        __syncthreads();

#pragma unroll
        for (int k = 0; k < 16; k++) {
            float a[8], b[8];
            *(float4*)(a)     = *(const float4*)(&As[k][tm * 8]);
            *(float4*)(a + 4) = *(const float4*)(&As[k][tm * 8 + 4]);
            *(float4*)(b)     = *(const float4*)(&Bs[k][tn * 8]);
            *(float4*)(b + 4) = *(const float4*)(&Bs[k][tn * 8 + 4]);
#pragma unroll
            for (int i = 0; i < 8; i++)
#pragma unroll
                for (int j = 0; j < 8; j++)
                    acc[i][j] = fmaf(a[i], b[j], acc[i][j]);
        }
        __syncthreads();
    }

#pragma unroll
    for (int i = 0; i < 8; i++) {
        int gm = m0 + tm * 8 + i;
        if (gm >= M) continue;
#pragma unroll
        for (int j = 0; j < 8; j++) {
            int gn = n0 + tn * 8 + j;
            if (gn < N) C[(size_t)gm * N + gn] = acc[i][j] + __ldg(&bias[gn]);
        }
    }
}

// =====================================================================
// Per-head batched GEMM for Ck/Cq:
//   C[bh, m, n] = sum_d  Afull[(b*S+m)*E + h*D + d] * P[n*E + h*D + d]
//   m in [0,384), n in [0,767), K = 64.  64x64 tile, 256 thr, 4x4/thr.
// =====================================================================
__global__ __launch_bounds__(256) void head_gemm(
    const float* __restrict__ Afull, const float* __restrict__ P,
    float* __restrict__ C)
{
    __shared__ float As[Dd][68];   // [d][m]
    __shared__ float Bs[Dd][68];   // [d][n]

    const int bh = blockIdx.z;
    const int b  = bh >> 3, h = bh & 7;
    const int m0 = blockIdx.y * 64;
    const int n0 = blockIdx.x * 64;
    const int tid = threadIdx.x;
    const int tm = tid >> 4, tn = tid & 15;
    const int dl = tid & 63, r4 = tid >> 6;   // scalar transpose loads

#pragma unroll
    for (int it = 0; it < 16; it++) {
        int r = r4 + it * 4;
        As[dl][r] = Afull[(size_t)(b * Ss + m0 + r) * Ee + h * Dd + dl];
        int n = n0 + r;
        Bs[dl][r] = (n < Rr) ? P[(size_t)n * Ee + h * Dd + dl] : 0.f;
    }
    __syncthreads();

    float acc[4][4];
#pragma unroll
    for (int i = 0; i < 4; i++)
#pragma unroll
        for (int j = 0; j < 4; j++) acc[i][j] = 0.f;

#pragma unroll 16
    for (int k = 0; k < 64; k++) {
        float a[4], bv[4];
        *(float4*)a  = *(const float4*)(&As[k][tm * 4]);
        *(float4*)bv = *(const float4*)(&Bs[k][tn * 4]);
#pragma unroll
        for (int i = 0; i < 4; i++)
#pragma unroll
            for (int j = 0; j < 4; j++)
                acc[i][j] = fmaf(a[i], bv[j], acc[i][j]);
    }

#pragma unroll
    for (int i = 0; i < 4; i++) {
        int row = m0 + tm * 4 + i;                  // always < 384
#pragma unroll
        for (int j = 0; j < 4; j++) {
            int col = n0 + tn * 4 + j;
            if (col < Rr)
                C[((size_t)bh * Ss + row) * RP + col] = acc[i][j];
        }
    }
}

// =====================================================================
// Fused flash attention with disentangled biases.
//   logits[i,j] = (q_i.k_j + Ck[i, j-i+383] + Cq[j, j-i+383]) * SCALE,
//   masked, online softmax, O = softmax @ V.  One CTA = 128 query rows.
// =====================================================================
struct AttnSmem {
    float Qs[Dd][132];     // [d][i]
    float Ks[Dd][132];     // [d][j]
    float Vs[128][68];     // [j][d]
    float Ps[128][132];    // logits / probs tile
    float mrow[128];
    float lrow[128];
    float crow[128];
    int   msk[128];
};

__global__ __launch_bounds__(256, 1) void attn_kernel(
    const float* __restrict__ Q, const float* __restrict__ Km,
    const float* __restrict__ V, const float* __restrict__ Ck,
    const float* __restrict__ Cq, const int* __restrict__ mask,
    float* __restrict__ ctx)
{
    extern __shared__ char smem_raw[];
    AttnSmem& sm = *reinterpret_cast<AttnSmem*>(smem_raw);

    const int bh = blockIdx.y;
    const int b  = bh >> 3, h = bh & 7;
    const int i0 = blockIdx.x * 128;
    const int tid = threadIdx.x;

    const int smr = (tid >> 4) << 3;   // S-tile row base (16 groups of 8)
    const int snc = (tid & 15) << 3;   // S-tile col base
    const int oy  = tid >> 3;          // O rows oy*4 .. +3
    const int ox  = (tid & 7) << 3;    // O col base
    const int dl  = tid & 63, r4 = tid >> 6;

    // Load Q tile transposed: Qs[d][i]
    const float* Qbase = Q + (size_t)(b * Ss + i0) * Ee + h * Dd;
#pragma unroll
    for (int it = 0; it < 32; it++) {
        int r = r4 + it * 4;
        sm.Qs[dl][r] = Qbase[(size_t)r * Ee + dl];
    }
    if (tid < 128) { sm.mrow[tid] = -CUDART_INF_F; sm.lrow[tid] = 0.f; }

    float o[4][8];
#pragma unroll
    for (int r = 0; r < 4; r++)
#pragma unroll
        for (int c = 0; c < 8; c++) o[r][c] = 0.f;

    const size_t ckBase = (size_t)bh * Ss;

    for (int jt = 0; jt < 3; jt++) {
        const int j0 = jt * 128;
        __syncthreads();   // previous tile's consumers done; also orders Qs/mrow init

        const float* Kbase = Km + (size_t)(b * Ss + j0) * Ee + h * Dd;
#pragma unroll
        for (int it = 0; it < 32; it++) {
            int r = r4 + it * 4;
            sm.Ks[dl][r] = Kbase[(size_t)r * Ee + dl];
        }
        const float* Vbase = V + (size_t)(b * Ss + j0) * Ee + h * Dd;
#pragma unroll
        for (int it = 0; it < 8; it++) {
            int idx = tid + it * 256;
            int r = idx >> 4, c4 = (idx & 15) << 2;
            *(float4*)&sm.Vs[r][c4] = *(const float4*)(Vbase + (size_t)r * Ee + c4);
        }
        if (tid < 128) sm.msk[tid] = mask[b * Ss + j0 + tid];
        __syncthreads();

        // ---- S = Q K^T (128x128, 8x8 per thread) ----
        float s[8][8];
#pragma unroll
        for (int i = 0; i < 8; i++)
#pragma unroll
            for (int j = 0; j < 8; j++) s[i][j] = 0.f;

#pragma unroll 8
        for (int d = 0; d < Dd; d++) {
            float a[8], kv[8];
            *(float4*)(a)      = *(const float4*)(&sm.Qs[d][smr]);
            *(float4*)(a + 4)  = *(const float4*)(&sm.Qs[d][smr + 4]);
            *(float4*)(kv)     = *(const float4*)(&sm.Ks[d][snc]);
            *(float4*)(kv + 4) = *(const float4*)(&sm.Ks[d][snc + 4]);
#pragma unroll
            for (int i = 0; i < 8; i++)
#pragma unroll
                for (int j = 0; j < 8; j++)
                    s[i][j] = fmaf(a[i], kv[j], s[i][j]);
        }

        // ---- biases (diagonal gathers), scale, mask -> Ps ----
#pragma unroll
        for (int ii = 0; ii < 8; ii++) {
            const int ig = i0 + smr + ii;
            const float* ckr = Ck + (ckBase + ig) * RP + (j0 + snc - ig + 383);
#pragma unroll
            for (int jj = 0; jj < 8; jj++) {
                const int jl = snc + jj;
                const int jg = j0 + jl;
                const int rr = jg - ig + 383;      // in [0,766]
                float v = s[ii][jj] + __ldg(ckr + jj)
                                    + __ldg(&Cq[(ckBase + jg) * RP + rr]);
                v *= SCALE_F;
                if (sm.msk[jl] == 0) v = -9.0e15f;
                sm.Ps[smr + ii][jl] = v;
            }
        }
        __syncthreads();

        // ---- online softmax row update ----
        if (tid < 128) {
            float mo = sm.mrow[tid];
            float mx = mo;
#pragma unroll 8
            for (int j = 0; j < 128; j++) mx = fmaxf(mx, sm.Ps[tid][j]);
            float cf = __expf(mo - mx);
            float sum = 0.f;
#pragma unroll 8
            for (int j = 0; j < 128; j++) {
                float p = __expf(sm.Ps[tid][j] - mx);
                sm.Ps[tid][j] = p;
                sum += p;
            }
            sm.mrow[tid] = mx;
            sm.lrow[tid] = fmaf(sm.lrow[tid], cf, sum);
            sm.crow[tid] = cf;
        }
        __syncthreads();

        // ---- O = O*cf + P @ V ----
        {
            float cf0 = sm.crow[oy * 4 + 0], cf1 = sm.crow[oy * 4 + 1];
            float cf2 = sm.crow[oy * 4 + 2], cf3 = sm.crow[oy * 4 + 3];
#pragma unroll
            for (int c = 0; c < 8; c++) {
                o[0][c] *= cf0; o[1][c] *= cf1; o[2][c] *= cf2; o[3][c] *= cf3;
            }
#pragma unroll 4
            for (int j = 0; j < 128; j++) {
                float p0 = sm.Ps[oy * 4 + 0][j];
                float p1 = sm.Ps[oy * 4 + 1][j];
                float p2 = sm.Ps[oy * 4 + 2][j];
                float p3 = sm.Ps[oy * 4 + 3][j];
                float vv[8];
                *(float4*)(vv)     = *(const float4*)(&sm.Vs[j][ox]);
                *(float4*)(vv + 4) = *(const float4*)(&sm.Vs[j][ox + 4]);
#pragma unroll
                for (int c = 0; c < 8; c++) {
                    o[0][c] = fmaf(p0, vv[c], o[0][c]);
                    o[1][c] = fmaf(p1, vv[c], o[1][c]);
                    o[2][c] = fmaf(p2, vv[c], o[2][c]);
                    o[3][c] = fmaf(p3, vv[c], o[3][c]);
                }
            }
        }
    }

    // finalize: divide by l, write context in [b, s, h, d] layout
#pragma unroll
    for (int r = 0; r < 4; r++) {
        const int row = oy * 4 + r;
        const float inv = 1.f / sm.lrow[row];
        float4 u0, u1;
        u0.x = o[r][0] * inv; u0.y = o[r][1] * inv;
        u0.z = o[r][2] * inv; u0.w = o[r][3] * inv;
        u1.x = o[r][4] * inv; u1.y = o[r][5] * inv;
        u1.z = o[r][6] * inv; u1.w = o[r][7] * inv;
        float* dst = ctx + (size_t)(b * Ss + i0 + row) * Ee + h * Dd + ox;
        *(float4*)dst       = u0;
        *(float4*)(dst + 4) = u1;
    }
}

// =====================================================================
// Host launcher (graph-capturable: kernel launches only)
// =====================================================================
extern "C" void kernel_launch(void* const* d_in, const int* in_sizes, int n_in,
                              void* d_out, int out_size)
{
    const float* x    = (const float*)d_in[0];
    const int*   mask = (const int*)  d_in[1];
    const float* Wq   = (const float*)d_in[2];
    const float* bq   = (const float*)d_in[3];
    const float* Wk   = (const float*)d_in[4];
    const float* bk   = (const float*)d_in[5];
    const float* Wv   = (const float*)d_in[6];
    const float* bv   = (const float*)d_in[7];
    const float* rel  = (const float*)d_in[8];
    const float* Wpk  = (const float*)d_in[9];
    const float* bpk  = (const float*)d_in[10];
    const float* Wpq  = (const float*)d_in[11];
    const float* bpq  = (const float*)d_in[12];
    const float* Wo   = (const float*)d_in[13];
    const float* bo   = (const float*)d_in[14];
    float* out = (float*)d_out;

    float *Q, *Km, *V, *ctx, *Pk, *Pq, *Ck, *Cq;
    cudaGetSymbolAddress((void**)&Q,   g_Q);
    cudaGetSymbolAddress((void**)&Km,  g_Km);
    cudaGetSymbolAddress((void**)&V,   g_V);
    cudaGetSymbolAddress((void**)&ctx, g_ctx);
    cudaGetSymbolAddress((void**)&Pk,  g_Pk);
    cudaGetSymbolAddress((void**)&Pq,  g_Pq);
    cudaGetSymbolAddress((void**)&Ck,  g_Ck);
    cudaGetSymbolAddress((void**)&Cq,  g_Cq);

    cudaFuncSetAttribute(attn_kernel,
                         cudaFuncAttributeMaxDynamicSharedMemorySize,
                         (int)sizeof(AttnSmem));

    dim3 blk(256);

    // Projections
    sgemm_bias<<<dim3(4, 24), blk>>>(x, Wq, bq, Q,  MSn, Ee, INd);
    sgemm_bias<<<dim3(4, 24), blk>>>(x, Wk, bk, Km, MSn, Ee, INd);
    sgemm_bias<<<dim3(4, 24), blk>>>(x, Wv, bv, V,  MSn, Ee, INd);

    // Positional projections: only rel_table rows 128..894 are reachable (S<MAXL)
    sgemm_bias<<<dim3(4, 6), blk>>>(rel + 128 * INd, Wpk, bpk, Pk, Rr, Ee, INd);
    sgemm_bias<<<dim3(4, 6), blk>>>(rel + 128 * INd, Wpq, bpq, Pq, Rr, Ee, INd);

    // Per-head bias matrices: Ck = Q_h . Pk_h^T ; Cq = K_h . Pq_h^T
    head_gemm<<<dim3(12, 6, BHn), blk>>>(Q,  Pk, Ck);
    head_gemm<<<dim3(12, 6, BHn), blk>>>(Km, Pq, Cq);

    // Fused attention
    attn_kernel<<<dim3(3, BHn), blk, sizeof(AttnSmem)>>>(Q, Km, V, Ck, Cq, mask, ctx);

    // Output projection
    sgemm_bias<<<dim3(4, 24), blk>>>(ctx, Wo, bo, out, MSn, Ee, INd);
}

// round 2
// speedup vs baseline: 1.0505x; 1.0505x over previous
#include <cuda_runtime.h>
#include <math_constants.h>
#include <cstdint>

// Problem constants
#define Bb   8
#define Ss   384
#define INd  512
#define Ee   512
#define Hh   8
#define Dd   64
#define Rr   767          // distinct rel values actually used (rows 128..894 of rel_table)
#define RP   768          // padded row stride for Ck/Cq
#define BHn  64           // B*H
#define MSn  3072         // B*S
#define SCALE_F 0.07216878364870322f   // 1/sqrt(64*3)

// ---------------- scratch (static device globals; no allocations) ----------------
static __device__ float g_Q  [MSn * Ee];
static __device__ float g_Km [MSn * Ee];
static __device__ float g_V  [MSn * Ee];
static __device__ float g_ctx[MSn * Ee];
static __device__ float g_Pk [Rr * Ee];
static __device__ float g_Pq [Rr * Ee];
static __device__ float g_Ck [(size_t)BHn * Ss * RP];   // [bh, i, r']  c2p gather source
static __device__ float g_Cq [(size_t)BHn * Ss * RP];   // [bh, j, r']  p2c gather source

// =====================================================================
// Generic SGEMM:  C[M,N] = A[M,K] @ W[N,K]^T + bias[N]
// 128x128 tile, BK=16, 256 threads, 8x8 per thread.
// =====================================================================
__global__ __launch_bounds__(256) void sgemm_bias(
    const float* __restrict__ A, const float* __restrict__ W,
    const float* __restrict__ bias, float* __restrict__ C,
    int M, int N, int K)
{
    __shared__ float As[16][128];
    __shared__ float Bs[16][128];

    const int tid = threadIdx.x;
    const int tm  = tid >> 4;          // 0..15
    const int tn  = tid & 15;          // 0..15
    const int m0  = blockIdx.y * 128;
    const int n0  = blockIdx.x * 128;

    const int lr = tid >> 2;           // 0..63
    const int lc = (tid & 3) << 2;     // 0,4,8,12  (float index of float4)

    float acc[8][8];
#pragma unroll
    for (int i = 0; i < 8; i++)
#pragma unroll
        for (int j = 0; j < 8; j++) acc[i][j] = 0.f;

    for (int k0 = 0; k0 < K; k0 += 16) {
#pragma unroll
        for (int it = 0; it < 2; it++) {
            int r  = lr + it * 64;
            int gm = m0 + r;
            float4 va = make_float4(0.f, 0.f, 0.f, 0.f);
            if (gm < M) va = *(const float4*)(A + (size_t)gm * K + k0 + lc);
            As[lc + 0][r] = va.x; As[lc + 1][r] = va.y;
            As[lc + 2][r] = va.z; As[lc + 3][r] = va.w;

            int gn = n0 + r;
            float4 vb = make_float4(0.f, 0.f, 0.f, 0.f);
            if (gn < N) vb = *(const float4*)(W + (size_t)gn * K + k0 + lc);
            Bs[lc + 0][r] = vb.x; Bs[lc + 1][r] = vb.y;
            Bs[lc + 2][r] = vb.z; Bs[lc + 3][r] = vb.w;
        }
        __syncthreads();

#pragma unroll
        for (int k = 0; k < 16; k++) {
            float a[8], b[8];
            *(float4*)(a)     = *(const float4*)(&As[k][tm * 8]);
            *(float4*)(a + 4) = *(const float4*)(&As[k][tm * 8 + 4]);
            *(float4*)(b)     = *(const float4*)(&Bs[k][tn * 8]);
            *(float4*)(b + 4) = *(const float4*)(&Bs[k][tn * 8 + 4]);
#pragma unroll
            for (int i = 0; i < 8; i++)
#pragma unroll
                for (int j = 0; j < 8; j++)
                    acc[i][j] = fmaf(a[i], b[j], acc[i][j]);
        }
        __syncthreads();
    }

#pragma unroll
    for (int i = 0; i < 8; i++) {
        int gm = m0 + tm * 8 + i;
        if (gm >= M) continue;
#pragma unroll
        for (int j = 0; j < 8; j++) {
            int gn = n0 + tn * 8 + j;
            if (gn < N) C[(size_t)gm * N + gn] = acc[i][j] + __ldg(&bias[gn]);
        }
    }
}

// =====================================================================
// Per-head batched GEMM for Ck/Cq:
//   C[bh, m, n] = sum_d  Afull[(b*S+m)*E + h*D + d] * P[n*E + h*D + d]
//   m in [0,384), n in [0,767), K = 64.  64x64 tile, 256 thr, 4x4/thr.
// =====================================================================
__global__ __launch_bounds__(256) void head_gemm(
    const float* __restrict__ Afull, const float* __restrict__ P,
    float* __restrict__ C)
{
    __shared__ float As[Dd][68];   // [d][m]
    __shared__ float Bs[Dd][68];   // [d][n]

    const int bh = blockIdx.z;
    const int b  = bh >> 3, h = bh & 7;
    const int m0 = blockIdx.y * 64;
    const int n0 = blockIdx.x * 64;
    const int tid = threadIdx.x;
    const int tm = tid >> 4, tn = tid & 15;
    const int dl = tid & 63, r4 = tid >> 6;   // scalar transpose loads

#pragma unroll
    for (int it = 0; it < 16; it++) {
        int r = r4 + it * 4;
        As[dl][r] = Afull[(size_t)(b * Ss + m0 + r) * Ee + h * Dd + dl];
        int n = n0 + r;
        Bs[dl][r] = (n < Rr) ? P[(size_t)n * Ee + h * Dd + dl] : 0.f;
    }
    __syncthreads();

    float acc[4][4];
#pragma unroll
    for (int i = 0; i < 4; i++)
#pragma unroll
        for (int j = 0; j < 4; j++) acc[i][j] = 0.f;

#pragma unroll 16
    for (int k = 0; k < 64; k++) {
        float a[4], bv[4];
        *(float4*)a  = *(const float4*)(&As[k][tm * 4]);
        *(float4*)bv = *(const float4*)(&Bs[k][tn * 4]);
#pragma unroll
        for (int i = 0; i < 4; i++)
#pragma unroll
            for (int j = 0; j < 4; j++)
                acc[i][j] = fmaf(a[i], bv[j], acc[i][j]);
    }

#pragma unroll
    for (int i = 0; i < 4; i++) {
        int row = m0 + tm * 4 + i;                  // always < 384
#pragma unroll
        for (int j = 0; j < 4; j++) {
            int col = n0 + tn * 4 + j;
            if (col < Rr)
                C[((size_t)bh * Ss + row) * RP + col] = acc[i][j];
        }
    }
}

// =====================================================================
// Fused flash attention with disentangled biases.
//   logits[i,j] = (q_i.k_j + Ck[i, j-i+383] + Cq[j, j-i+383]) * SCALE,
//   masked, online softmax, O = softmax @ V.  One CTA = 128 query rows.
// =====================================================================
struct AttnSmem {
    float Qs[Dd][132];     // [d][i]
    float Ks[Dd][132];     // [d][j]
    float Vs[128][68];     // [j][d]
    float Ps[128][132];    // logits / probs tile
    float mrow[128];
    float lrow[128];
    float crow[128];
    int   msk[128];
};

__global__ __launch_bounds__(256, 1) void attn_kernel(
    const float* __restrict__ Q, const float* __restrict__ Km,
    const float* __restrict__ V, const float* __restrict__ Ck,
    const float* __restrict__ Cq, const int* __restrict__ mask,
    float* __restrict__ ctx)
{
    extern __shared__ char smem_raw[];
    AttnSmem& sm = *reinterpret_cast<AttnSmem*>(smem_raw);

    const int bh = blockIdx.y;
    const int b  = bh >> 3, h = bh & 7;
    const int i0 = blockIdx.x * 128;
    const int tid = threadIdx.x;

    const int smr = (tid >> 4) << 3;   // S-tile row base (16 groups of 8)
    const int snc = (tid & 15) << 3;   // S-tile col base
    const int oy  = tid >> 3;          // O rows oy*4 .. +3
    const int ox  = (tid & 7) << 3;    // O col base
    const int dl  = tid & 63, r4 = tid >> 6;

    // Load Q tile transposed: Qs[d][i]
    const float* Qbase = Q + (size_t)(b * Ss + i0) * Ee + h * Dd;
#pragma unroll
    for (int it = 0; it < 32; it++) {
        int r = r4 + it * 4;
        sm.Qs[dl][r] = Qbase[(size_t)r * Ee + dl];
    }
    if (tid < 128) { sm.mrow[tid] = -CUDART_INF_F; sm.lrow[tid] = 0.f; }

    float o[4][8];
#pragma unroll
    for (int r = 0; r < 4; r++)
#pragma unroll
        for (int c = 0; c < 8; c++) o[r][c] = 0.f;

    const size_t ckBase = (size_t)bh * Ss;

    for (int jt = 0; jt < 3; jt++) {
        const int j0 = jt * 128;
        __syncthreads();   // previous tile's consumers done; also orders Qs/mrow init

        const float* Kbase = Km + (size_t)(b * Ss + j0) * Ee + h * Dd;
#pragma unroll
        for (int it = 0; it < 32; it++) {
            int r = r4 + it * 4;
            sm.Ks[dl][r] = Kbase[(size_t)r * Ee + dl];
        }
        const float* Vbase = V + (size_t)(b * Ss + j0) * Ee + h * Dd;
#pragma unroll
        for (int it = 0; it < 8; it++) {
            int idx = tid + it * 256;
            int r = idx >> 4, c4 = (idx & 15) << 2;
            *(float4*)&sm.Vs[r][c4] = *(const float4*)(Vbase + (size_t)r * Ee + c4);
        }
        if (tid < 128) sm.msk[tid] = mask[b * Ss + j0 + tid];
        __syncthreads();

        // ---- S = Q K^T (128x128, 8x8 per thread) ----
        float s[8][8];
#pragma unroll
        for (int i = 0; i < 8; i++)
#pragma unroll
            for (int j = 0; j < 8; j++) s[i][j] = 0.f;

#pragma unroll 8
        for (int d = 0; d < Dd; d++) {
            float a[8], kv[8];
            *(float4*)(a)      = *(const float4*)(&sm.Qs[d][smr]);
            *(float4*)(a + 4)  = *(const float4*)(&sm.Qs[d][smr + 4]);
            *(float4*)(kv)     = *(const float4*)(&sm.Ks[d][snc]);
            *(float4*)(kv + 4) = *(const float4*)(&sm.Ks[d][snc + 4]);
#pragma unroll
            for (int i = 0; i < 8; i++)
#pragma unroll
                for (int j = 0; j < 8; j++)
                    s[i][j] = fmaf(a[i], kv[j], s[i][j]);
        }

        // ---- biases (diagonal gathers), scale, mask -> Ps ----
#pragma unroll
        for (int ii = 0; ii < 8; ii++) {
            const int ig = i0 + smr + ii;
            const float* ckr = Ck + (ckBase + ig) * RP + (j0 + snc - ig + 383);
#pragma unroll
            for (int jj = 0; jj < 8; jj++) {
                const int jl = snc + jj;
                const int jg = j0 + jl;
                const int rr = jg - ig + 383;      // in [0,766]
                float v = s[ii][jj] + __ldg(ckr + jj)
                                    + __ldg(&Cq[(ckBase + jg) * RP + rr]);
                v *= SCALE_F;
                if (sm.msk[jl] == 0) v = -9.0e15f;
                sm.Ps[smr + ii][jl] = v;
            }
        }
        __syncthreads();

        // ---- online softmax row update ----
        if (tid < 128) {
            float mo = sm.mrow[tid];
            float mx = mo;
#pragma unroll 8
            for (int j = 0; j < 128; j++) mx = fmaxf(mx, sm.Ps[tid][j]);
            float cf = __expf(mo - mx);
            float sum = 0.f;
#pragma unroll 8
            for (int j = 0; j < 128; j++) {
                float p = __expf(sm.Ps[tid][j] - mx);
                sm.Ps[tid][j] = p;
                sum += p;
            }
            sm.mrow[tid] = mx;
            sm.lrow[tid] = fmaf(sm.lrow[tid], cf, sum);
            sm.crow[tid] = cf;
        }
        __syncthreads();

        // ---- O = O*cf + P @ V ----
        {
            float cf0 = sm.crow[oy * 4 + 0], cf1 = sm.crow[oy * 4 + 1];
            float cf2 = sm.crow[oy * 4 + 2], cf3 = sm.crow[oy * 4 + 3];
#pragma unroll
            for (int c = 0; c < 8; c++) {
                o[0][c] *= cf0; o[1][c] *= cf1; o[2][c] *= cf2; o[3][c] *= cf3;
            }
#pragma unroll 4
            for (int j = 0; j < 128; j++) {
                float p0 = sm.Ps[oy * 4 + 0][j];
                float p1 = sm.Ps[oy * 4 + 1][j];
                float p2 = sm.Ps[oy * 4 + 2][j];
                float p3 = sm.Ps[oy * 4 + 3][j];
                float vv[8];
                *(float4*)(vv)     = *(const float4*)(&sm.Vs[j][ox]);
                *(float4*)(vv + 4) = *(const float4*)(&sm.Vs[j][ox + 4]);
#pragma unroll
                for (int c = 0; c < 8; c++) {
                    o[0][c] = fmaf(p0, vv[c], o[0][c]);
                    o[1][c] = fmaf(p1, vv[c], o[1][c]);
                    o[2][c] = fmaf(p2, vv[c], o[2][c]);
                    o[3][c] = fmaf(p3, vv[c], o[3][c]);
                }
            }
        }
    }

    // finalize: divide by l, write context in [b, s, h, d] layout
#pragma unroll
    for (int r = 0; r < 4; r++) {
        const int row = oy * 4 + r;
        const float inv = 1.f / sm.lrow[row];
        float4 u0, u1;
        u0.x = o[r][0] * inv; u0.y = o[r][1] * inv;
        u0.z = o[r][2] * inv; u0.w = o[r][3] * inv;
        u1.x = o[r][4] * inv; u1.y = o[r][5] * inv;
        u1.z = o[r][6] * inv; u1.w = o[r][7] * inv;
        float* dst = ctx + (size_t)(b * Ss + i0 + row) * Ee + h * Dd + ox;
        *(float4*)dst       = u0;
        *(float4*)(dst + 4) = u1;
    }
}

// =====================================================================
// Host launcher (graph-capturable: kernel launches only)
// =====================================================================
extern "C" void kernel_launch(void* const* d_in, const int* in_sizes, int n_in,
                              void* d_out, int out_size)
{
    const float* x    = (const float*)d_in[0];
    const int*   mask = (const int*)  d_in[1];
    const float* Wq   = (const float*)d_in[2];
    const float* bq   = (const float*)d_in[3];
    const float* Wk   = (const float*)d_in[4];
    const float* bk   = (const float*)d_in[5];
    const float* Wv   = (const float*)d_in[6];
    const float* bv   = (const float*)d_in[7];
    const float* rel  = (const float*)d_in[8];
    const float* Wpk  = (const float*)d_in[9];
    const float* bpk  = (const float*)d_in[10];
    const float* Wpq  = (const float*)d_in[11];
    const float* bpq  = (const float*)d_in[12];
    const float* Wo   = (const float*)d_in[13];
    const float* bo   = (const float*)d_in[14];
    float* out = (float*)d_out;

    float *Q, *Km, *V, *ctx, *Pk, *Pq, *Ck, *Cq;
    cudaGetSymbolAddress((void**)&Q,   g_Q);
    cudaGetSymbolAddress((void**)&Km,  g_Km);
    cudaGetSymbolAddress((void**)&V,   g_V);
    cudaGetSymbolAddress((void**)&ctx, g_ctx);
    cudaGetSymbolAddress((void**)&Pk,  g_Pk);
    cudaGetSymbolAddress((void**)&Pq,  g_Pq);
    cudaGetSymbolAddress((void**)&Ck,  g_Ck);
    cudaGetSymbolAddress((void**)&Cq,  g_Cq);

    cudaFuncSetAttribute(attn_kernel,
                         cudaFuncAttributeMaxDynamicSharedMemorySize,
                         (int)sizeof(AttnSmem));

    dim3 blk(256);

    // Projections
    sgemm_bias<<<dim3(4, 24), blk>>>(x, Wq, bq, Q,  MSn, Ee, INd);
    sgemm_bias<<<dim3(4, 24), blk>>>(x, Wk, bk, Km, MSn, Ee, INd);
    sgemm_bias<<<dim3(4, 24), blk>>>(x, Wv, bv, V,  MSn, Ee, INd);

    // Positional projections: only rel_table rows 128..894 are reachable (S<MAXL)
    sgemm_bias<<<dim3(4, 6), blk>>>(rel + 128 * INd, Wpk, bpk, Pk, Rr, Ee, INd);
    sgemm_bias<<<dim3(4, 6), blk>>>(rel + 128 * INd, Wpq, bpq, Pq, Rr, Ee, INd);

    // Per-head bias matrices: Ck = Q_h . Pk_h^T ; Cq = K_h . Pq_h^T
    head_gemm<<<dim3(12, 6, BHn), blk>>>(Q,  Pk, Ck);
    head_gemm<<<dim3(12, 6, BHn), blk>>>(Km, Pq, Cq);

    // Fused attention
    attn_kernel<<<dim3(3, BHn), blk, sizeof(AttnSmem)>>>(Q, Km, V, Ck, Cq, mask, ctx);

    // Output projection
    sgemm_bias<<<dim3(4, 24), blk>>>(ctx, Wo, bo, out, MSn, Ee, INd);
}

// round 3
// speedup vs baseline: 2.1872x; 2.0821x over previous
#include <cuda_runtime.h>
#include <math_constants.h>
#include <cstdint>

#define Ss   384
#define Ee   512
#define Dd   64
#define Hh   8
#define Rr   767
#define RP   768
#define BHn  64
#define MSn  3072
#define SCALE_F 0.07216878364870322f

// ---------------- scratch ----------------
static __device__ float g_Q  [MSn * Ee];
static __device__ float g_Km [MSn * Ee];
static __device__ float g_V  [MSn * Ee];
static __device__ float g_ctx[MSn * Ee];
static __device__ float g_Pk [Rr * Ee];
static __device__ float g_Pq [Rr * Ee];
static __device__ float g_Ck [(size_t)BHn * Ss * RP];
static __device__ float g_Cq [(size_t)BHn * Ss * RP];

// ---------------- tf32 mma helpers ----------------
__device__ __forceinline__ uint32_t f2tf32(float x) {
    uint32_t r; asm("cvt.rna.tf32.f32 %0, %1;" : "=r"(r) : "f"(x)); return r;
}
__device__ __forceinline__ void mma8(float* c,
    uint32_t a0, uint32_t a1, uint32_t a2, uint32_t a3, uint32_t b0, uint32_t b1)
{
    asm volatile(
        "mma.sync.aligned.m16n8k8.row.col.f32.tf32.tf32.f32 "
        "{%0,%1,%2,%3}, {%4,%5,%6,%7}, {%8,%9}, {%0,%1,%2,%3};"
        : "+f"(c[0]), "+f"(c[1]), "+f"(c[2]), "+f"(c[3])
        : "r"(a0), "r"(a1), "r"(a2), "r"(a3), "r"(b0), "r"(b1));
}

struct GemmSet { const float* A; const float* W; const float* bias; float* C; int M; };
struct ProjArgs { GemmSet s[5]; };

// =====================================================================
// Core 128x128 tf32 tile:  C = A[M,K] @ W[N,K]^T (+bias)
// BK=32, 256 threads = 8 warps (4m x 2n), warp tile 32x64.
// Smem [row][36] padded, tf32-converted.
// =====================================================================
__device__ __forceinline__ void tf32_tile(
    const GemmSet& g, int lda, int ldb, int ldc, int Ncols, int K,
    int m0c, int n0c, uint32_t* As, uint32_t* Bs)
{
    const int tid  = threadIdx.x;
    const int wid  = tid >> 5, lane = tid & 31;
    const int wm   = (wid & 3) * 32, wn = (wid >> 2) * 64;
    const int qr   = lane >> 2, qc = lane & 3;

    float acc[2][8][4];
#pragma unroll
    for (int mf = 0; mf < 2; mf++)
#pragma unroll
        for (int nf = 0; nf < 8; nf++)
#pragma unroll
            for (int c = 0; c < 4; c++) acc[mf][nf][c] = 0.f;

    const int r  = tid >> 1;          // 0..127
    const int kh = (tid & 1) * 16;    // 0 or 16

    for (int k0 = 0; k0 < K; k0 += 32) {
        const bool arow = (m0c + r) < g.M;
        const bool brow = (n0c + r) < Ncols;
        const float* Ap = g.A + (size_t)(m0c + r) * lda + k0 + kh;
        const float* Bp = g.W + (size_t)(n0c + r) * ldb + k0 + kh;
#pragma unroll
        for (int i = 0; i < 4; i++) {
            float4 va = arow ? *(const float4*)(Ap + 4 * i) : make_float4(0.f, 0.f, 0.f, 0.f);
            uint4 ua; ua.x = f2tf32(va.x); ua.y = f2tf32(va.y);
                      ua.z = f2tf32(va.z); ua.w = f2tf32(va.w);
            *(uint4*)&As[r * 36 + kh + 4 * i] = ua;

            float4 vb = brow ? *(const float4*)(Bp + 4 * i) : make_float4(0.f, 0.f, 0.f, 0.f);
            uint4 ub; ub.x = f2tf32(vb.x); ub.y = f2tf32(vb.y);
                      ub.z = f2tf32(vb.z); ub.w = f2tf32(vb.w);
            *(uint4*)&Bs[r * 36 + kh + 4 * i] = ub;
        }
        __syncthreads();

#pragma unroll
        for (int kk = 0; kk < 4; kk++) {
            const int kb = kk * 8;
            uint32_t a[2][4];
#pragma unroll
            for (int mf = 0; mf < 2; mf++) {
                const int mrow = wm + mf * 16 + qr;
                a[mf][0] = As[(mrow)     * 36 + kb + qc];
                a[mf][1] = As[(mrow + 8) * 36 + kb + qc];
                a[mf][2] = As[(mrow)     * 36 + kb + qc + 4];
                a[mf][3] = As[(mrow + 8) * 36 + kb + qc + 4];
            }
#pragma unroll
            for (int nf = 0; nf < 8; nf++) {
                const int nrow = wn + nf * 8 + qr;
                const uint32_t b0 = Bs[nrow * 36 + kb + qc];
                const uint32_t b1 = Bs[nrow * 36 + kb + qc + 4];
                mma8(acc[0][nf], a[0][0], a[0][1], a[0][2], a[0][3], b0, b1);
                mma8(acc[1][nf], a[1][0], a[1][1], a[1][2], a[1][3], b0, b1);
            }
        }
        __syncthreads();
    }

    // ---- epilogue ----
#pragma unroll
    for (int mf = 0; mf < 2; mf++) {
#pragma unroll
        for (int half = 0; half < 2; half++) {
            const int row = m0c + wm + mf * 16 + qr + half * 8;
            if (row >= g.M) continue;
#pragma unroll
            for (int nf = 0; nf < 8; nf++) {
                const int col = n0c + wn + nf * 8 + 2 * qc;
                float v0 = acc[mf][nf][half * 2 + 0];
                float v1 = acc[mf][nf][half * 2 + 1];
                if (g.bias) { v0 += __ldg(&g.bias[col]); v1 += __ldg(&g.bias[col + 1]); }
                if (col + 1 < Ncols)
                    *(float2*)&g.C[(size_t)row * ldc + col] = make_float2(v0, v1);
                else if (col < Ncols)
                    g.C[(size_t)row * ldc + col] = v0;
            }
        }
    }
}

// Fused projections: z selects one of up to 5 (A,W,bias,C,M) sets. N=K=512.
__global__ __launch_bounds__(256) void tf32_proj(ProjArgs pa)
{
    __shared__ uint32_t As[128 * 36], Bs[128 * 36];
    GemmSet g = pa.s[blockIdx.z];
    const int m0c = blockIdx.y * 128;
    if (m0c >= g.M) return;
    tf32_tile(g, 512, 512, 512, 512, 512, m0c, blockIdx.x * 128, As, Bs);
}

// Fused per-head GEMMs: z = bh*2 + which.  which0: Ck = Q_h.Pk_h^T; which1: Cq = K_h.Pq_h^T.
__global__ __launch_bounds__(256) void tf32_head(
    const float* __restrict__ Q, const float* __restrict__ Km,
    const float* __restrict__ Pk, const float* __restrict__ Pq,
    float* __restrict__ Ck, float* __restrict__ Cq)
{
    __shared__ uint32_t As[128 * 36], Bs[128 * 36];
    const int z = blockIdx.z, bh = z >> 1, which = z & 1;
    const int b = bh >> 3, h = bh & 7;
    GemmSet g;
    g.A    = (which ? Km : Q) + (size_t)b * Ss * Ee + h * Dd;
    g.W    = (which ? Pq : Pk) + h * Dd;
    g.bias = nullptr;
    g.C    = (which ? Cq : Ck) + (size_t)bh * Ss * RP;
    g.M    = Ss;
    tf32_tile(g, Ee, Ee, RP, Rr, Dd, blockIdx.y * 128, blockIdx.x * 128, As, Bs);
}

// =====================================================================
// Fused flash attention with disentangled biases (unchanged, passing).
// =====================================================================
struct AttnSmem {
    float Qs[Dd][132];
    float Ks[Dd][132];
    float Vs[128][68];
    float Ps[128][132];
    float mrow[128];
    float lrow[128];
    float crow[128];
    int   msk[128];
};

__global__ __launch_bounds__(256, 1) void attn_kernel(
    const float* __restrict__ Q, const float* __restrict__ Km,
    const float* __restrict__ V, const float* __restrict__ Ck,
    const float* __restrict__ Cq, const int* __restrict__ mask,
    float* __restrict__ ctx)
{
    extern __shared__ char smem_raw[];
    AttnSmem& sm = *reinterpret_cast<AttnSmem*>(smem_raw);

    const int bh = blockIdx.y;
    const int b  = bh >> 3, h = bh & 7;
    const int i0 = blockIdx.x * 128;
    const int tid = threadIdx.x;

    const int smr = (tid >> 4) << 3;
    const int snc = (tid & 15) << 3;
    const int oy  = tid >> 3;
    const int ox  = (tid & 7) << 3;
    const int dl  = tid & 63, r4 = tid >> 6;

    const float* Qbase = Q + (size_t)(b * Ss + i0) * Ee + h * Dd;
#pragma unroll
    for (int it = 0; it < 32; it++) {
        int r = r4 + it * 4;
        sm.Qs[dl][r] = Qbase[(size_t)r * Ee + dl];
    }
    if (tid < 128) { sm.mrow[tid] = -CUDART_INF_F; sm.lrow[tid] = 0.f; }

    float o[4][8];
#pragma unroll
    for (int r = 0; r < 4; r++)
#pragma unroll
        for (int c = 0; c < 8; c++) o[r][c] = 0.f;

    const size_t ckBase = (size_t)bh * Ss;

    for (int jt = 0; jt < 3; jt++) {
        const int j0 = jt * 128;
        __syncthreads();

        const float* Kbase = Km + (size_t)(b * Ss + j0) * Ee + h * Dd;
#pragma unroll
        for (int it = 0; it < 32; it++) {
            int r = r4 + it * 4;
            sm.Ks[dl][r] = Kbase[(size_t)r * Ee + dl];
        }
        const float* Vbase = V + (size_t)(b * Ss + j0) * Ee + h * Dd;
#pragma unroll
        for (int it = 0; it < 8; it++) {
            int idx = tid + it * 256;
            int r = idx >> 4, c4 = (idx & 15) << 2;
            *(float4*)&sm.Vs[r][c4] = *(const float4*)(Vbase + (size_t)r * Ee + c4);
        }
        if (tid < 128) sm.msk[tid] = mask[b * Ss + j0 + tid];
        __syncthreads();

        float s[8][8];
#pragma unroll
        for (int i = 0; i < 8; i++)
#pragma unroll
            for (int j = 0; j < 8; j++) s[i][j] = 0.f;

#pragma unroll 8
        for (int d = 0; d < Dd; d++) {
            float a[8], kv[8];
            *(float4*)(a)      = *(const float4*)(&sm.Qs[d][smr]);
            *(float4*)(a + 4)  = *(const float4*)(&sm.Qs[d][smr + 4]);
            *(float4*)(kv)     = *(const float4*)(&sm.Ks[d][snc]);
            *(float4*)(kv + 4) = *(const float4*)(&sm.Ks[d][snc + 4]);
#pragma unroll
            for (int i = 0; i < 8; i++)
#pragma unroll
                for (int j = 0; j < 8; j++)
                    s[i][j] = fmaf(a[i], kv[j], s[i][j]);
        }

#pragma unroll
        for (int ii = 0; ii < 8; ii++) {
            const int ig = i0 + smr + ii;
            const float* ckr = Ck + (ckBase + ig) * RP + (j0 + snc - ig + 383);
#pragma unroll
            for (int jj = 0; jj < 8; jj++) {
                const int jl = snc + jj;
                const int jg = j0 + jl;
                const int rr = jg - ig + 383;
                float v = s[ii][jj] + __ldg(ckr + jj)
                                    + __ldg(&Cq[(ckBase + jg) * RP + rr]);
                v *= SCALE_F;
                if (sm.msk[jl] == 0) v = -9.0e15f;
                sm.Ps[smr + ii][jl] = v;
            }
        }
        __syncthreads();

        if (tid < 128) {
            float mo = sm.mrow[tid];
            float mx = mo;
#pragma unroll 8
            for (int j = 0; j < 128; j++) mx = fmaxf(mx, sm.Ps[tid][j]);
            float cf = __expf(mo - mx);
            float sum = 0.f;
#pragma unroll 8
            for (int j = 0; j < 128; j++) {
                float p = __expf(sm.Ps[tid][j] - mx);
                sm.Ps[tid][j] = p;
                sum += p;
            }
            sm.mrow[tid] = mx;
            sm.lrow[tid] = fmaf(sm.lrow[tid], cf, sum);
            sm.crow[tid] = cf;
        }
        __syncthreads();

        {
            float cf0 = sm.crow[oy * 4 + 0], cf1 = sm.crow[oy * 4 + 1];
            float cf2 = sm.crow[oy * 4 + 2], cf3 = sm.crow[oy * 4 + 3];
#pragma unroll
            for (int c = 0; c < 8; c++) {
                o[0][c] *= cf0; o[1][c] *= cf1; o[2][c] *= cf2; o[3][c] *= cf3;
            }
#pragma unroll 4
            for (int j = 0; j < 128; j++) {
                float p0 = sm.Ps[oy * 4 + 0][j];
                float p1 = sm.Ps[oy * 4 + 1][j];
                float p2 = sm.Ps[oy * 4 + 2][j];
                float p3 = sm.Ps[oy * 4 + 3][j];
                float vv[8];
                *(float4*)(vv)     = *(const float4*)(&sm.Vs[j][ox]);
                *(float4*)(vv + 4) = *(const float4*)(&sm.Vs[j][ox + 4]);
#pragma unroll
                for (int c = 0; c < 8; c++) {
                    o[0][c] = fmaf(p0, vv[c], o[0][c]);
                    o[1][c] = fmaf(p1, vv[c], o[1][c]);
                    o[2][c] = fmaf(p2, vv[c], o[2][c]);
                    o[3][c] = fmaf(p3, vv[c], o[3][c]);
                }
            }
        }
    }

#pragma unroll
    for (int r = 0; r < 4; r++) {
        const int row = oy * 4 + r;
        const float inv = 1.f / sm.lrow[row];
        float4 u0, u1;
        u0.x = o[r][0] * inv; u0.y = o[r][1] * inv;
        u0.z = o[r][2] * inv; u0.w = o[r][3] * inv;
        u1.x = o[r][4] * inv; u1.y = o[r][5] * inv;
        u1.z = o[r][6] * inv; u1.w = o[r][7] * inv;
        float* dst = ctx + (size_t)(b * Ss + i0 + row) * Ee + h * Dd + ox;
        *(float4*)dst       = u0;
        *(float4*)(dst + 4) = u1;
    }
}

// =====================================================================
// Host launcher
// =====================================================================
extern "C" void kernel_launch(void* const* d_in, const int* in_sizes, int n_in,
                              void* d_out, int out_size)
{
    const float* x    = (const float*)d_in[0];
    const int*   mask = (const int*)  d_in[1];
    const float* Wq   = (const float*)d_in[2];
    const float* bq   = (const float*)d_in[3];
    const float* Wk   = (const float*)d_in[4];
    const float* bk   = (const float*)d_in[5];
    const float* Wv   = (const float*)d_in[6];
    const float* bv   = (const float*)d_in[7];
    const float* rel  = (const float*)d_in[8];
    const float* Wpk  = (const float*)d_in[9];
    const float* bpk  = (const float*)d_in[10];
    const float* Wpq  = (const float*)d_in[11];
    const float* bpq  = (const float*)d_in[12];
    const float* Wo   = (const float*)d_in[13];
    const float* bo   = (const float*)d_in[14];
    float* out = (float*)d_out;

    float *Q, *Km, *V, *ctx, *Pk, *Pq, *Ck, *Cq;
    cudaGetSymbolAddress((void**)&Q,   g_Q);
    cudaGetSymbolAddress((void**)&Km,  g_Km);
    cudaGetSymbolAddress((void**)&V,   g_V);
    cudaGetSymbolAddress((void**)&ctx, g_ctx);
    cudaGetSymbolAddress((void**)&Pk,  g_Pk);
    cudaGetSymbolAddress((void**)&Pq,  g_Pq);
    cudaGetSymbolAddress((void**)&Ck,  g_Ck);
    cudaGetSymbolAddress((void**)&Cq,  g_Cq);

    cudaFuncSetAttribute(attn_kernel,
                         cudaFuncAttributeMaxDynamicSharedMemorySize,
                         (int)sizeof(AttnSmem));

    const float* relS = rel + 128 * 512;   // only rows 128..894 reachable (S < MAXL)

    // 1) Fused projections: QKV (M=3072) + positional Pk/Pq (M=767)
    ProjArgs pa;
    pa.s[0] = { x,    Wq,  bq,  Q,   MSn };
    pa.s[1] = { x,    Wk,  bk,  Km,  MSn };
    pa.s[2] = { x,    Wv,  bv,  V,   MSn };
    pa.s[3] = { relS, Wpk, bpk, Pk,  Rr  };
    pa.s[4] = { relS, Wpq, bpq, Pq,  Rr  };
    tf32_proj<<<dim3(4, 24, 5), 256>>>(pa);

    // 2) Fused per-head bias GEMMs: Ck = Q_h.Pk_h^T ; Cq = K_h.Pq_h^T
    tf32_head<<<dim3(6, 3, 2 * BHn), 256>>>(Q, Km, Pk, Pq, Ck, Cq);

    // 3) Fused attention
    attn_kernel<<<dim3(3, BHn), 256, sizeof(AttnSmem)>>>(Q, Km, V, Ck, Cq, mask, ctx);

    // 4) Output projection
    ProjArgs po;
    po.s[0] = { ctx, Wo, bo, out, MSn };
    po.s[1] = po.s[0]; po.s[2] = po.s[0]; po.s[3] = po.s[0]; po.s[4] = po.s[0];
    tf32_proj<<<dim3(4, 24, 1), 256>>>(po);
}

// round 4
// speedup vs baseline: 3.4477x; 1.5763x over previous
#include <cuda_runtime.h>
#include <math_constants.h>
#include <cstdint>

#define Ss   384
#define Ee   512
#define Dd   64
#define Hh   8
#define Rr   767
#define RP   768
#define BHn  64
#define MSn  3072
#define SCALE_F 0.07216878364870322f

// ---------------- scratch ----------------
static __device__ float g_Q  [MSn * Ee];
static __device__ float g_Km [MSn * Ee];
static __device__ float g_V  [MSn * Ee];
static __device__ float g_ctx[MSn * Ee];
static __device__ float g_Pk [Rr * Ee];
static __device__ float g_Pq [Rr * Ee];
static __device__ float g_Ck [(size_t)BHn * Ss * RP];
static __device__ float g_Cq [(size_t)BHn * Ss * RP];

// ---------------- tf32 mma helpers ----------------
__device__ __forceinline__ uint32_t f2tf32(float x) {
    uint32_t r; asm("cvt.rna.tf32.f32 %0, %1;" : "=r"(r) : "f"(x)); return r;
}
__device__ __forceinline__ void mma8(float* c,
    uint32_t a0, uint32_t a1, uint32_t a2, uint32_t a3, uint32_t b0, uint32_t b1)
{
    asm volatile(
        "mma.sync.aligned.m16n8k8.row.col.f32.tf32.tf32.f32 "
        "{%0,%1,%2,%3}, {%4,%5,%6,%7}, {%8,%9}, {%0,%1,%2,%3};"
        : "+f"(c[0]), "+f"(c[1]), "+f"(c[2]), "+f"(c[3])
        : "r"(a0), "r"(a1), "r"(a2), "r"(a3), "r"(b0), "r"(b1));
}

struct GemmSet { const float* A; const float* W; const float* bias; float* C; int M; };
struct ProjArgs { GemmSet s[5]; };

// =====================================================================
// Core 128x128 tf32 tile:  C = A[M,K] @ W[N,K]^T (+bias)
// =====================================================================
__device__ __forceinline__ void tf32_tile(
    const GemmSet& g, int lda, int ldb, int ldc, int Ncols, int K,
    int m0c, int n0c, uint32_t* As, uint32_t* Bs)
{
    const int tid  = threadIdx.x;
    const int wid  = tid >> 5, lane = tid & 31;
    const int wm   = (wid & 3) * 32, wn = (wid >> 2) * 64;
    const int qr   = lane >> 2, qc = lane & 3;

    float acc[2][8][4];
#pragma unroll
    for (int mf = 0; mf < 2; mf++)
#pragma unroll
        for (int nf = 0; nf < 8; nf++)
#pragma unroll
            for (int c = 0; c < 4; c++) acc[mf][nf][c] = 0.f;

    const int r  = tid >> 1;
    const int kh = (tid & 1) * 16;

    for (int k0 = 0; k0 < K; k0 += 32) {
        const bool arow = (m0c + r) < g.M;
        const bool brow = (n0c + r) < Ncols;
        const float* Ap = g.A + (size_t)(m0c + r) * lda + k0 + kh;
        const float* Bp = g.W + (size_t)(n0c + r) * ldb + k0 + kh;
#pragma unroll
        for (int i = 0; i < 4; i++) {
            float4 va = arow ? *(const float4*)(Ap + 4 * i) : make_float4(0.f, 0.f, 0.f, 0.f);
            uint4 ua; ua.x = f2tf32(va.x); ua.y = f2tf32(va.y);
                      ua.z = f2tf32(va.z); ua.w = f2tf32(va.w);
            *(uint4*)&As[r * 36 + kh + 4 * i] = ua;

            float4 vb = brow ? *(const float4*)(Bp + 4 * i) : make_float4(0.f, 0.f, 0.f, 0.f);
            uint4 ub; ub.x = f2tf32(vb.x); ub.y = f2tf32(vb.y);
                      ub.z = f2tf32(vb.z); ub.w = f2tf32(vb.w);
            *(uint4*)&Bs[r * 36 + kh + 4 * i] = ub;
        }
        __syncthreads();

#pragma unroll
        for (int kk = 0; kk < 4; kk++) {
            const int kb = kk * 8;
            uint32_t a[2][4];
#pragma unroll
            for (int mf = 0; mf < 2; mf++) {
                const int mrow = wm + mf * 16 + qr;
                a[mf][0] = As[(mrow)     * 36 + kb + qc];
                a[mf][1] = As[(mrow + 8) * 36 + kb + qc];
                a[mf][2] = As[(mrow)     * 36 + kb + qc + 4];
                a[mf][3] = As[(mrow + 8) * 36 + kb + qc + 4];
            }
#pragma unroll
            for (int nf = 0; nf < 8; nf++) {
                const int nrow = wn + nf * 8 + qr;
                const uint32_t b0 = Bs[nrow * 36 + kb + qc];
                const uint32_t b1 = Bs[nrow * 36 + kb + qc + 4];
                mma8(acc[0][nf], a[0][0], a[0][1], a[0][2], a[0][3], b0, b1);
                mma8(acc[1][nf], a[1][0], a[1][1], a[1][2], a[1][3], b0, b1);
            }
        }
        __syncthreads();
    }

#pragma unroll
    for (int mf = 0; mf < 2; mf++) {
#pragma unroll
        for (int half = 0; half < 2; half++) {
            const int row = m0c + wm + mf * 16 + qr + half * 8;
            if (row >= g.M) continue;
#pragma unroll
            for (int nf = 0; nf < 8; nf++) {
                const int col = n0c + wn + nf * 8 + 2 * qc;
                float v0 = acc[mf][nf][half * 2 + 0];
                float v1 = acc[mf][nf][half * 2 + 1];
                if (g.bias) { v0 += __ldg(&g.bias[col]); v1 += __ldg(&g.bias[col + 1]); }
                if (col + 1 < Ncols)
                    *(float2*)&g.C[(size_t)row * ldc + col] = make_float2(v0, v1);
                else if (col < Ncols)
                    g.C[(size_t)row * ldc + col] = v0;
            }
        }
    }
}

__global__ __launch_bounds__(256) void tf32_proj(ProjArgs pa)
{
    __shared__ uint32_t As[128 * 36], Bs[128 * 36];
    GemmSet g = pa.s[blockIdx.z];
    const int m0c = blockIdx.y * 128;
    if (m0c >= g.M) return;
    tf32_tile(g, 512, 512, 512, 512, 512, m0c, blockIdx.x * 128, As, Bs);
}

// Per-head bias GEMMs, windowed to the reachable rr band.
// which0: Ck = Q_h.Pk_h^T, window [256-m0, 768-m0); which1: Cq = K_h.Pq_h^T, window [m0, m0+512).
__global__ __launch_bounds__(256) void tf32_head(
    const float* __restrict__ Q, const float* __restrict__ Km,
    const float* __restrict__ Pk, const float* __restrict__ Pq,
    float* __restrict__ Ck, float* __restrict__ Cq)
{
    __shared__ uint32_t As[128 * 36], Bs[128 * 36];
    const int z = blockIdx.z, bh = z >> 1, which = z & 1;
    const int b = bh >> 3, h = bh & 7;
    const int m0c = blockIdx.y * 128;
    const int n0c = (which ? m0c : 256 - m0c) + blockIdx.x * 128;
    GemmSet g;
    g.A    = (which ? Km : Q) + (size_t)b * Ss * Ee + h * Dd;
    g.W    = (which ? Pq : Pk) + h * Dd;
    g.bias = nullptr;
    g.C    = (which ? Cq : Ck) + (size_t)bh * Ss * RP;
    g.M    = Ss;
    tf32_tile(g, Ee, Ee, RP, Rr, Dd, m0c, n0c, As, Bs);
}

// =====================================================================
// Flash attention with disentangled biases, tf32 mma for QK^T and PV.
// 64 query rows per CTA, 256 threads (8 warps: 2m x 4n), 3 j-tiles of 128.
// =====================================================================
#define LDQ 68
#define LDV 133
#define LDP 132
#define ATTN_SMEM ((64*68 + 128*68 + 64*132 + 64*3 + 128) * 4)

__global__ __launch_bounds__(256, 2) void attn_mma(
    const float* __restrict__ Q, const float* __restrict__ Km,
    const float* __restrict__ V, const float* __restrict__ Ck,
    const float* __restrict__ Cq, const int* __restrict__ mask,
    float* __restrict__ ctx)
{
    extern __shared__ char smraw[];
    uint32_t* Qs = (uint32_t*)smraw;            // 64 x 68 (tf32, row-major K)
    uint32_t* KV = Qs + 64 * LDQ;               // K: 128 x 68 ; V^T aliased: 64 x 133
    float*    Ps = (float*)(KV + 128 * LDQ);    // 64 x 132 logits/probs
    uint32_t* PsU = (uint32_t*)Ps;
    float* mrow = Ps + 64 * LDP;
    float* lrow = mrow + 64;
    float* crow = lrow + 64;
    int*   msk  = (int*)(crow + 64);

    const int bh = blockIdx.y, b = bh >> 3, h = bh & 7;
    const int i0 = blockIdx.x * 64;
    const int tid = threadIdx.x, wid = tid >> 5, lane = tid & 31;
    const int qr = lane >> 2, qc = lane & 3;
    const int wm  = (wid & 1) * 32;
    const int wn  = (wid >> 1) * 32;
    const int wn2 = (wid >> 1) * 16;

    // Q tile -> tf32 smem
    {
        const int r = tid >> 2, kh = (tid & 3) * 16;
        const float* p = Q + ((size_t)(b * Ss + i0 + r)) * Ee + h * Dd + kh;
#pragma unroll
        for (int i = 0; i < 4; i++) {
            float4 v = *(const float4*)(p + 4 * i);
            uint4 u; u.x = f2tf32(v.x); u.y = f2tf32(v.y);
                     u.z = f2tf32(v.z); u.w = f2tf32(v.w);
            *(uint4*)&Qs[r * LDQ + kh + 4 * i] = u;
        }
    }
    if (tid < 64) { mrow[tid] = -CUDART_INF_F; lrow[tid] = 0.f; }

    float accO[2][2][4];
#pragma unroll
    for (int mf = 0; mf < 2; mf++)
#pragma unroll
        for (int nf = 0; nf < 2; nf++)
#pragma unroll
            for (int c = 0; c < 4; c++) accO[mf][nf][c] = 0.f;

    const size_t cB = (size_t)bh * Ss;

    for (int jt = 0; jt < 3; jt++) {
        const int j0 = jt * 128;
        __syncthreads();   // protect KV (V of prev iter) + Ps reads

        // K tile 128x64 -> tf32 smem
        {
            const int r = tid >> 1, kh = (tid & 1) * 32;
            const float* p = Km + ((size_t)(b * Ss + j0 + r)) * Ee + h * Dd + kh;
#pragma unroll
            for (int i = 0; i < 8; i++) {
                float4 v = *(const float4*)(p + 4 * i);
                uint4 u; u.x = f2tf32(v.x); u.y = f2tf32(v.y);
                         u.z = f2tf32(v.z); u.w = f2tf32(v.w);
                *(uint4*)&KV[r * LDQ + kh + 4 * i] = u;
            }
        }
        if (tid < 128) msk[tid] = mask[b * Ss + j0 + tid];
        __syncthreads();

        // ---- S = Q K^T : M=64, N=128, K=64 ----
        float accS[2][4][4];
#pragma unroll
        for (int mf = 0; mf < 2; mf++)
#pragma unroll
            for (int nf = 0; nf < 4; nf++)
#pragma unroll
                for (int c = 0; c < 4; c++) accS[mf][nf][c] = 0.f;

#pragma unroll
        for (int kk = 0; kk < 8; kk++) {
            const int kb = kk * 8;
            uint32_t a[2][4];
#pragma unroll
            for (int mf = 0; mf < 2; mf++) {
                const int mr = wm + mf * 16 + qr;
                a[mf][0] = Qs[mr * LDQ + kb + qc];
                a[mf][1] = Qs[(mr + 8) * LDQ + kb + qc];
                a[mf][2] = Qs[mr * LDQ + kb + qc + 4];
                a[mf][3] = Qs[(mr + 8) * LDQ + kb + qc + 4];
            }
#pragma unroll
            for (int nf = 0; nf < 4; nf++) {
                const int nr = wn + nf * 8 + qr;
                const uint32_t b0 = KV[nr * LDQ + kb + qc];
                const uint32_t b1 = KV[nr * LDQ + kb + qc + 4];
                mma8(accS[0][nf], a[0][0], a[0][1], a[0][2], a[0][3], b0, b1);
                mma8(accS[1][nf], a[1][0], a[1][1], a[1][2], a[1][3], b0, b1);
            }
        }

        // ---- biases + scale + mask -> Ps ----
#pragma unroll
        for (int mf = 0; mf < 2; mf++) {
#pragma unroll
            for (int half = 0; half < 2; half++) {
                const int rl = wm + mf * 16 + qr + half * 8;
                const int ig = i0 + rl;
                const float* ckRow = Ck + (cB + ig) * RP + (j0 - ig + 383);
#pragma unroll
                for (int nf = 0; nf < 4; nf++) {
                    const int col = wn + nf * 8 + 2 * qc;
                    const int jg = j0 + col;
                    const int rr = jg - ig + 383;
                    float v0 = accS[mf][nf][half * 2 + 0]
                             + __ldg(ckRow + col)
                             + __ldg(Cq + (cB + jg) * RP + rr);
                    float v1 = accS[mf][nf][half * 2 + 1]
                             + __ldg(ckRow + col + 1)
                             + __ldg(Cq + (cB + jg + 1) * RP + rr + 1);
                    v0 *= SCALE_F; v1 *= SCALE_F;
                    if (msk[col] == 0)     v0 = -9.0e15f;
                    if (msk[col + 1] == 0) v1 = -9.0e15f;
                    *(float2*)&Ps[rl * LDP + col] = make_float2(v0, v1);
                }
            }
        }
        __syncthreads();   // Ps complete; all Ks reads done

        // ---- V tile -> V^T tf32 (aliases K buffer) ----
        {
            const int d4 = (tid & 15) * 4, jb = tid >> 4;
            const float* vb = V + ((size_t)(b * Ss + j0)) * Ee + h * Dd + d4;
#pragma unroll
            for (int p2 = 0; p2 < 8; p2++) {
                const int jj = jb + p2 * 16;
                float4 v = *(const float4*)(vb + (size_t)jj * Ee);
                KV[(d4 + 0) * LDV + jj] = f2tf32(v.x);
                KV[(d4 + 1) * LDV + jj] = f2tf32(v.y);
                KV[(d4 + 2) * LDV + jj] = f2tf32(v.z);
                KV[(d4 + 3) * LDV + jj] = f2tf32(v.w);
            }
        }

        // ---- online softmax: 4 threads per row, stride-4 columns ----
        {
            const int row = tid >> 2, q = tid & 3;
            float* pr = Ps + row * LDP;
            const float mo = mrow[row];
            float mx = mo;
#pragma unroll 8
            for (int t = 0; t < 32; t++) mx = fmaxf(mx, pr[q + 4 * t]);
            mx = fmaxf(mx, __shfl_xor_sync(0xffffffffu, mx, 1));
            mx = fmaxf(mx, __shfl_xor_sync(0xffffffffu, mx, 2));
            float sum = 0.f;
#pragma unroll 8
            for (int t = 0; t < 32; t++) {
                const int c = q + 4 * t;
                const float p = __expf(pr[c] - mx);
                sum += p;
                ((uint32_t*)pr)[c] = f2tf32(p);
            }
            sum += __shfl_xor_sync(0xffffffffu, sum, 1);
            sum += __shfl_xor_sync(0xffffffffu, sum, 2);
            if (q == 0) {
                const float cf = __expf(mo - mx);
                crow[row] = cf;
                mrow[row] = mx;
                lrow[row] = lrow[row] * cf + sum;
            }
        }
        __syncthreads();

        // ---- O = O*cf + P @ V : M=64, N=64, K=128 ----
        {
            float cf0[2], cf1[2];
#pragma unroll
            for (int mf = 0; mf < 2; mf++) {
                cf0[mf] = crow[wm + mf * 16 + qr];
                cf1[mf] = crow[wm + mf * 16 + qr + 8];
            }
#pragma unroll
            for (int mf = 0; mf < 2; mf++)
#pragma unroll
                for (int nf = 0; nf < 2; nf++) {
                    accO[mf][nf][0] *= cf0[mf]; accO[mf][nf][1] *= cf0[mf];
                    accO[mf][nf][2] *= cf1[mf]; accO[mf][nf][3] *= cf1[mf];
                }
#pragma unroll
            for (int kk = 0; kk < 16; kk++) {
                const int kb = kk * 8;
                uint32_t a[2][4];
#pragma unroll
                for (int mf = 0; mf < 2; mf++) {
                    const int mr = wm + mf * 16 + qr;
                    a[mf][0] = PsU[mr * LDP + kb + qc];
                    a[mf][1] = PsU[(mr + 8) * LDP + kb + qc];
                    a[mf][2] = PsU[mr * LDP + kb + qc + 4];
                    a[mf][3] = PsU[(mr + 8) * LDP + kb + qc + 4];
                }
#pragma unroll
                for (int nf = 0; nf < 2; nf++) {
                    const int nr = wn2 + nf * 8 + qr;
                    const uint32_t b0 = KV[nr * LDV + kb + qc];
                    const uint32_t b1 = KV[nr * LDV + kb + qc + 4];
                    mma8(accO[0][nf], a[0][0], a[0][1], a[0][2], a[0][3], b0, b1);
                    mma8(accO[1][nf], a[1][0], a[1][1], a[1][2], a[1][3], b0, b1);
                }
            }
        }
    }

    // ---- finalize ----
#pragma unroll
    for (int mf = 0; mf < 2; mf++) {
#pragma unroll
        for (int half = 0; half < 2; half++) {
            const int rl = wm + mf * 16 + qr + half * 8;
            const float inv = 1.f / lrow[rl];
#pragma unroll
            for (int nf = 0; nf < 2; nf++) {
                const int col = wn2 + nf * 8 + 2 * qc;
                float2 o;
                o.x = accO[mf][nf][half * 2 + 0] * inv;
                o.y = accO[mf][nf][half * 2 + 1] * inv;
                *(float2*)&ctx[((size_t)(b * Ss + i0 + rl)) * Ee + h * Dd + col] = o;
            }
        }
    }
}

// =====================================================================
// Host launcher
// =====================================================================
extern "C" void kernel_launch(void* const* d_in, const int* in_sizes, int n_in,
                              void* d_out, int out_size)
{
    const float* x    = (const float*)d_in[0];
    const int*   mask = (const int*)  d_in[1];
    const float* Wq   = (const float*)d_in[2];
    const float* bq   = (const float*)d_in[3];
    const float* Wk   = (const float*)d_in[4];
    const float* bk   = (const float*)d_in[5];
    const float* Wv   = (const float*)d_in[6];
    const float* bv   = (const float*)d_in[7];
    const float* rel  = (const float*)d_in[8];
    const float* Wpk  = (const float*)d_in[9];
    const float* bpk  = (const float*)d_in[10];
    const float* Wpq  = (const float*)d_in[11];
    const float* bpq  = (const float*)d_in[12];
    const float* Wo   = (const float*)d_in[13];
    const float* bo   = (const float*)d_in[14];
    float* out = (float*)d_out;

    float *Q, *Km, *V, *ctx, *Pk, *Pq, *Ck, *Cq;
    cudaGetSymbolAddress((void**)&Q,   g_Q);
    cudaGetSymbolAddress((void**)&Km,  g_Km);
    cudaGetSymbolAddress((void**)&V,   g_V);
    cudaGetSymbolAddress((void**)&ctx, g_ctx);
    cudaGetSymbolAddress((void**)&Pk,  g_Pk);
    cudaGetSymbolAddress((void**)&Pq,  g_Pq);
    cudaGetSymbolAddress((void**)&Ck,  g_Ck);
    cudaGetSymbolAddress((void**)&Cq,  g_Cq);

    cudaFuncSetAttribute(attn_mma,
                         cudaFuncAttributeMaxDynamicSharedMemorySize, ATTN_SMEM);

    const float* relS = rel + 128 * 512;   // only rows 128..894 reachable (S < MAXL)

    // 1) Fused projections
    ProjArgs pa;
    pa.s[0] = { x,    Wq,  bq,  Q,   MSn };
    pa.s[1] = { x,    Wk,  bk,  Km,  MSn };
    pa.s[2] = { x,    Wv,  bv,  V,   MSn };
    pa.s[3] = { relS, Wpk, bpk, Pk,  Rr  };
    pa.s[4] = { relS, Wpq, bpq, Pq,  Rr  };
    tf32_proj<<<dim3(4, 24, 5), 256>>>(pa);

    // 2) Windowed per-head bias GEMMs
    tf32_head<<<dim3(4, 3, 2 * BHn), 256>>>(Q, Km, Pk, Pq, Ck, Cq);

    // 3) Fused tensor-core attention
    attn_mma<<<dim3(6, BHn), 256, ATTN_SMEM>>>(Q, Km, V, Ck, Cq, mask, ctx);

    // 4) Output projection
    ProjArgs po;
    po.s[0] = { ctx, Wo, bo, out, MSn };
    po.s[1] = po.s[0]; po.s[2] = po.s[0]; po.s[3] = po.s[0]; po.s[4] = po.s[0];
    tf32_proj<<<dim3(4, 24, 1), 256>>>(po);
}